// round 17
// baseline (speedup 1.0000x reference)
#include <cuda_runtime.h>
#include <cuda_fp16.h>
#include <math_constants.h>
#include <cstdint>

// Problem dimensions (deterministic from setup_inputs)
#define BNUM 4
#define CCH 128          // channels
#define HF 128           // feature map height
#define WF 128           // feature map width
#define NV 10475         // vertices
#define NPTS 200000      // gaussians
#define KB 20            // bary rows
#define IMH 512
#define IMW 512
#define HWIMG (IMH*IMW)
#define HWF (HF*WF)
#define C8 (CCH / 8)     // uint4 (8 halves) per pixel = 16
#define NPT (BNUM * NPTS)
#define NBINS (BNUM * HWF)   // 65536 top-left-pixel bins
#define NSBLK 64             // scan blocks (1024 bins each)

// Scratch (static device globals -- no allocation allowed).
// g_hist relies on zero-initialization at module load; every launch re-zeroes
// it at the END (aux stream) so the invariant holds across graph replays.
__device__ uint4  g_fmTh[(size_t)BNUM * HWF * C8];  // 16 MB fp16 transposed map (B,Hf,Wf,C)
__device__ float  g_depth[BNUM * HWIMG];            // 4 MB depth maps
__device__ float4 g_v3p[BNUM * NV];                 // float4-padded vertices3d
__device__ float2 g_ctr[NPT];                       // centers2d (coords -> geom)
__device__ uint4  g_wt4 [NPT];                      // packed half2x4 weights (orig order)
__device__ int    g_bin [NPT];                      // per-point bin id
__device__ int    g_ord [NPT];                      // sorted slot -> original point idx
__device__ int    g_hist[NBINS];                    // bin histogram (zero between launches)
__device__ int    g_start[NBINS];                   // global exclusive bin starts
__device__ int    g_cursor[NBINS];                  // mutable cursors (perm) -> bin ends
__device__ int    g_bsum[NSBLK];                    // raw per-scan-block totals

// ---------------------------------------------------------------------------
// Kernel AZ (aux, end of graph): re-zero histogram for the next replay.
// ---------------------------------------------------------------------------
__global__ void zero_hist_k() {
    const int i = blockIdx.x * blockDim.x + threadIdx.x;
    if (i < NBINS / 4)
        reinterpret_cast<int4*>(g_hist)[i] = make_int4(0, 0, 0, 0);
}

// ---------------------------------------------------------------------------
// Kernel A1b (aux): init depth (+inf) and pad v3d to float4.
// ---------------------------------------------------------------------------
__global__ void init_pad_k(const float* __restrict__ v3d) {
    const int i = blockIdx.x * blockDim.x + threadIdx.x;
    if (i < BNUM * HWIMG / 4) {
        reinterpret_cast<float4*>(g_depth)[i] =
            make_float4(CUDART_INF_F, CUDART_INF_F, CUDART_INF_F, CUDART_INF_F);
    }
    if (i < BNUM * NV) {
        g_v3p[i] = make_float4(v3d[3 * i], v3d[3 * i + 1], v3d[3 * i + 2], 0.0f);
    }
}

// ---------------------------------------------------------------------------
// Per-point coords helper: weights + bin from center.
// Edge fold (proven R12): off-left/off-top weight mass moves onto the clamped
// corner so every nonzero weight matches the bin-decoded corner.
// ---------------------------------------------------------------------------
__device__ __forceinline__ void coord_point(
        const float* __restrict__ v2d, const int* __restrict__ parents,
        const float* __restrict__ bary, const int idx,
        float2& ctr, uint4& wp, int& bin) {
    const int b = idx / NPTS;
    const int n = idx - b * NPTS;
    const int kk = n % KB;

    const float w0 = __ldg(&bary[kk * 3 + 0]);
    const float w1 = __ldg(&bary[kk * 3 + 1]);
    const float w2 = __ldg(&bary[kk * 3 + 2]);

    const int p0 = __ldg(&parents[n * 3 + 0]);
    const int p1 = __ldg(&parents[n * 3 + 1]);
    const int p2 = __ldg(&parents[n * 3 + 2]);

    const float* v2b = v2d + (size_t)b * NV * 2;
    const float2 a2 = *reinterpret_cast<const float2*>(v2b + 2 * p0);
    const float2 b2 = *reinterpret_cast<const float2*>(v2b + 2 * p1);
    const float2 c2 = *reinterpret_cast<const float2*>(v2b + 2 * p2);
    const float cx = w0 * a2.x + w1 * b2.x + w2 * c2.x;
    const float cy = w0 * a2.y + w1 * b2.y + w2 * c2.y;
    ctr = make_float2(cx, cy);

    const float gxn = cx / (float)(IMW - 1) * 2.0f - 1.0f;
    const float gyn = cy / (float)(IMH - 1) * 2.0f - 1.0f;
    const float px = (gxn + 1.0f) * 0.5f * (float)(WF - 1);
    const float py = (gyn + 1.0f) * 0.5f * (float)(HF - 1);

    const float x0f = floorf(px), y0f = floorf(py);
    const float wx = px - x0f, wy = py - y0f;
    const int x0 = (int)x0f, y0 = (int)y0f;

    const bool ix0 = (x0 >= 0) && (x0 < WF);
    const bool ix1 = (x0 + 1 >= 0) && (x0 + 1 < WF);
    const bool iy0 = (y0 >= 0) && (y0 < HF);
    const bool iy1 = (y0 + 1 >= 0) && (y0 + 1 < HF);

    float w00 = (1.0f - wx) * (1.0f - wy) * (float)(ix0 && iy0);
    float w10 = wx * (1.0f - wy)          * (float)(ix1 && iy0);
    float w01 = (1.0f - wx) * wy          * (float)(ix0 && iy1);
    float w11 = wx * wy                   * (float)(ix1 && iy1);

    if (x0 < 0) { w00 = w10; w01 = w11; w10 = 0.0f; w11 = 0.0f; }
    if (y0 < 0) { w00 = w01; w10 = w11; w01 = 0.0f; w11 = 0.0f; }

    const int xc0 = min(max(x0, 0), WF - 1);
    const int yc0 = min(max(y0, 0), HF - 1);
    bin = b * HWF + yc0 * WF + xc0;

    const __half2 h0 = __float2half2_rn(w00);
    const __half2 h1 = __float2half2_rn(w10);
    const __half2 h2 = __float2half2_rn(w01);
    const __half2 h3 = __float2half2_rn(w11);
    wp.x = *reinterpret_cast<const uint32_t*>(&h0);
    wp.y = *reinterpret_cast<const uint32_t*>(&h1);
    wp.z = *reinterpret_cast<const uint32_t*>(&h2);
    wp.w = *reinterpret_cast<const uint32_t*>(&h3);
}

// ---------------------------------------------------------------------------
// Kernel 1 (main, CRITICAL PATH): 2 consecutive points per thread -- doubles
// gather MLP (the old 1-pt version measured 18.4us at issue=23%, L1=50%,
// i.e. latency-bound). Pairs merge the ctr/bin stores (float4 / int2).
// ---------------------------------------------------------------------------
__global__ void coords_k(const float* __restrict__ v2d,
                         const int*   __restrict__ parents,
                         const float* __restrict__ bary) {
    const int t = blockIdx.x * blockDim.x + threadIdx.x;
    const int idx = 2 * t;
    if (idx >= NPT) return;

    float2 c0, c1;
    uint4  wp0, wp1;
    int    b0, b1;
    coord_point(v2d, parents, bary, idx,     c0, wp0, b0);
    coord_point(v2d, parents, bary, idx + 1, c1, wp1, b1);

    reinterpret_cast<float4*>(g_ctr)[t] = make_float4(c0.x, c0.y, c1.x, c1.y);
    g_wt4[idx]     = wp0;
    g_wt4[idx + 1] = wp1;
    reinterpret_cast<int2*>(g_bin)[t] = make_int2(b0, b1);
    atomicAdd(&g_hist[b0], 1);
    atomicAdd(&g_hist[b1], 1);
}

// ---------------------------------------------------------------------------
// Kernel A2 (aux): scatter-min vertex depths. z > 0 so int-cmp == float-cmp.
// ---------------------------------------------------------------------------
__global__ void scatter_k(const float* __restrict__ v2d, const float* __restrict__ v3d) {
    const int i = blockIdx.x * blockDim.x + threadIdx.x;
    if (i >= BNUM * NV) return;
    const float xf = rintf(v2d[2 * i]);       // round-half-even, matches jnp.round
    const float yf = rintf(v2d[2 * i + 1]);
    const int xi = (int)xf, yi = (int)yf;
    if (xi < 0 || xi >= IMW || yi < 0 || yi >= IMH) return;
    const int b = i / NV;
    const float z = v3d[3 * i + 2];
    atomicMin(reinterpret_cast<int*>(&g_depth[b * HWIMG + yi * IMW + xi]),
              __float_as_int(z));
}

// ---------------------------------------------------------------------------
// Kernel A3 (aux, overlaps scan/perm/sample): 3D geometry outputs.
// ---------------------------------------------------------------------------
__global__ void geom_k(const int* __restrict__ parents, const float* __restrict__ bary,
                       float* __restrict__ out_vw, float* __restrict__ out_c3) {
    const int idx = blockIdx.x * blockDim.x + threadIdx.x;
    if (idx >= NPT) return;
    const int b = idx / NPTS;
    const int n = idx - b * NPTS;
    const int kk = n % KB;

    const float w0 = __ldg(&bary[kk * 3 + 0]);
    const float w1 = __ldg(&bary[kk * 3 + 1]);
    const float w2 = __ldg(&bary[kk * 3 + 2]);

    const int p0 = __ldg(&parents[n * 3 + 0]);
    const int p1 = __ldg(&parents[n * 3 + 1]);
    const int p2 = __ldg(&parents[n * 3 + 2]);

    const float4* v3b = g_v3p + b * NV;
    const float4 va = __ldg(&v3b[p0]);
    const float4 vb = __ldg(&v3b[p1]);
    const float4 vg = __ldg(&v3b[p2]);

    const float c3x = w0 * va.x + w1 * vb.x + w2 * vg.x;
    const float c3y = w0 * va.y + w1 * vb.y + w2 * vg.y;
    const float c3z = w0 * va.z + w1 * vb.z + w2 * vg.z;

    const float e1x = vb.x - va.x, e1y = vb.y - va.y, e1z = vb.z - va.z;
    const float e2x = vg.x - va.x, e2y = vg.y - va.y, e2z = vg.z - va.z;
    float nx = e1y * e2z - e1z * e2y;
    float ny = e1z * e2x - e1x * e2z;
    float nz = e1x * e2y - e1y * e2x;
    const float nrm = sqrtf(nx * nx + ny * ny + nz * nz) + 1e-8f;
    nx /= nrm; ny /= nrm; nz /= nrm;

    const float cl = sqrtf(c3x * c3x + c3y * c3y + c3z * c3z) + 1e-8f;
    const float vx = -c3x / cl, vy = -c3y / cl, vz = -c3z / cl;
    const float ang = fmaxf(nx * vx + ny * vy + nz * vz, 0.0f);

    const float2 c = g_ctr[idx];
    const int xc = min(max((int)rintf(c.x), 0), IMW - 1);
    const int yc = min(max((int)rintf(c.y), 0), IMH - 1);
    const float dsamp = g_depth[b * HWIMG + yc * IMW + xc];
    const bool vis = (c3z <= dsamp + 1e-3f) || isinf(dsamp);

    out_vw[idx] = vis ? ang : 0.0f;
    out_c3[(size_t)idx * 3 + 0] = c3x;
    out_c3[(size_t)idx * 3 + 1] = c3y;
    out_c3[(size_t)idx * 3 + 2] = c3z;
}

// ---------------------------------------------------------------------------
// Kernel 2 (main): block-local exclusive scan via warp shuffles.
// ---------------------------------------------------------------------------
__global__ void __launch_bounds__(1024) prefix1_k() {
    __shared__ int wsum[32];
    const int t = threadIdx.x;
    const int bin = blockIdx.x * 1024 + t;
    const int lane = t & 31;
    const int wid = t >> 5;

    const int v = g_hist[bin];
    int inc = v;
#pragma unroll
    for (int off = 1; off < 32; off <<= 1) {
        const int u = __shfl_up_sync(0xFFFFFFFF, inc, off);
        if (lane >= off) inc += u;
    }
    if (lane == 31) wsum[wid] = inc;
    __syncthreads();
    if (wid == 0) {
        int s = wsum[lane];
#pragma unroll
        for (int off = 1; off < 32; off <<= 1) {
            const int u = __shfl_up_sync(0xFFFFFFFF, s, off);
            if (lane >= off) s += u;
        }
        wsum[lane] = s;
    }
    __syncthreads();
    const int woff = (wid == 0) ? 0 : wsum[wid - 1];
    g_start[bin] = woff + inc - v;           // exclusive within block
    if (t == 1023) g_bsum[blockIdx.x] = woff + inc;   // raw block total
}

// ---------------------------------------------------------------------------
// Kernel 3 (main): fused cross-block offset + globalize.
// ---------------------------------------------------------------------------
__global__ void __launch_bounds__(1024) fix2_k() {
    __shared__ int off_s;
    const int k = blockIdx.x;        // scan block 0..63
    const int t = threadIdx.x;
    if (t < 32) {
        int s = 0;
        if (t < k)      s += g_bsum[t];
        if (t + 32 < k) s += g_bsum[t + 32];
#pragma unroll
        for (int o = 16; o > 0; o >>= 1) s += __shfl_down_sync(0xFFFFFFFF, s, o);
        if (t == 0) off_s = s;
    }
    __syncthreads();
    const int bin = k * 1024 + t;
    const int v = g_start[bin] + off_s;
    g_start[bin]  = v;
    g_cursor[bin] = v;
}

// ---------------------------------------------------------------------------
// Kernel 4 (main): counting-sort scatter of only the original index (4B).
// ---------------------------------------------------------------------------
__global__ void perm_k() {
    const int idx = blockIdx.x * blockDim.x + threadIdx.x;
    if (idx >= NPT) return;
    const int bin = g_bin[idx];
    const int slot = atomicAdd(&g_cursor[bin], 1);
    g_ord[slot] = idx;
}

// ---------------------------------------------------------------------------
// Kernel A1a (aux): vectorized transpose + fp16 convert (measured 13.3us).
// ---------------------------------------------------------------------------
__global__ void __launch_bounds__(256) transpose_k(const float* __restrict__ fm) {
    __shared__ float4 tile4[32][33];
    const int b  = blockIdx.z;
    const int p0 = blockIdx.x * 128;
    const int c0 = blockIdx.y * 32;
    const float4* src4 = reinterpret_cast<const float4*>(fm + (size_t)b * CCH * HWF);
    uint4* dst = g_fmTh + (size_t)b * HWF * C8;

    const int tx = threadIdx.x;
    const int ty = threadIdx.y;
    const int tid = ty * 32 + tx;

#pragma unroll
    for (int k = 0; k < 4; k++) {
        const int r = ty + 8 * k;
        tile4[r][tx] = src4[(size_t)(c0 + r) * (HWF / 4) + (p0 / 4) + tx];
    }
    __syncthreads();

    const float* tilef = reinterpret_cast<const float*>(tile4);  // row stride 132
#pragma unroll
    for (int it = 0; it < 2; it++) {
        const int e = tid + it * 256;
        const int pix = e >> 2;
        const int q = e & 3;
        uint4 o;
        uint32_t* ow = reinterpret_cast<uint32_t*>(&o);
#pragma unroll
        for (int h = 0; h < 4; h++) {
            const int c = q * 8 + h * 2;
            const __half2 hh = __floats2half2_rn(tilef[c * 132 + pix],
                                                 tilef[(c + 1) * 132 + pix]);
            ow[h] = *reinterpret_cast<const uint32_t*>(&hh);
        }
        dst[(size_t)(p0 + pix) * C8 + (c0 / 8) + q] = o;
    }
}

// ---------------------------------------------------------------------------
// Kernel 5 (main): warp-per-bin gather sampling (write-bound, ~97us).
// ---------------------------------------------------------------------------
__global__ void __launch_bounds__(256) sample_k(float* __restrict__ out_feats) {
    const int bin = blockIdx.x * 8 + (threadIdx.x >> 5);
    if (bin >= NBINS) return;
    const int lane = threadIdx.x & 31;

    const int start = g_start[bin];
    const int end   = g_cursor[bin];
    if (start >= end) return;

    const int p  = bin & (HWF - 1);
    const int x0 = p & (WF - 1);
    const int y0 = p >> 7;
    const int dx = (x0 < WF - 1) ? 1 : 0;
    const int dy = (y0 < HF - 1) ? WF : 0;

    const uint2* fm2 = reinterpret_cast<const uint2*>(g_fmTh);
    const uint2 c00 = __ldg(fm2 + (size_t)(bin)           * 32 + lane);
    const uint2 c10 = __ldg(fm2 + (size_t)(bin + dx)      * 32 + lane);
    const uint2 c01 = __ldg(fm2 + (size_t)(bin + dy)      * 32 + lane);
    const uint2 c11 = __ldg(fm2 + (size_t)(bin + dx + dy) * 32 + lane);

    const __half2 a00 = *reinterpret_cast<const __half2*>(&c00.x);
    const __half2 b00 = *reinterpret_cast<const __half2*>(&c00.y);
    const __half2 a10 = *reinterpret_cast<const __half2*>(&c10.x);
    const __half2 b10 = *reinterpret_cast<const __half2*>(&c10.y);
    const __half2 a01 = *reinterpret_cast<const __half2*>(&c01.x);
    const __half2 b01 = *reinterpret_cast<const __half2*>(&c01.y);
    const __half2 a11 = *reinterpret_cast<const __half2*>(&c11.x);
    const __half2 b11 = *reinterpret_cast<const __half2*>(&c11.y);

    for (int s = start; s < end; s++) {
        const int  oidx = __ldg(&g_ord[s]);
        const uint4 wp  = __ldg(&g_wt4[oidx]);   // broadcast: one line per point

        const __half2 W00 = *reinterpret_cast<const __half2*>(&wp.x);
        const __half2 W10 = *reinterpret_cast<const __half2*>(&wp.y);
        const __half2 W01 = *reinterpret_cast<const __half2*>(&wp.z);
        const __half2 W11 = *reinterpret_cast<const __half2*>(&wp.w);

        __half2 ra = __hmul2(a00, W00);
        ra = __hfma2(a10, W10, ra);
        ra = __hfma2(a01, W01, ra);
        ra = __hfma2(a11, W11, ra);
        __half2 rb = __hmul2(b00, W00);
        rb = __hfma2(b10, W10, rb);
        rb = __hfma2(b01, W01, rb);
        rb = __hfma2(b11, W11, rb);

        const float2 fa = __half22float2(ra);
        const float2 fb = __half22float2(rb);
        float4* outp = reinterpret_cast<float4*>(out_feats) + (size_t)oidx * (CCH / 4) + lane;
        *outp = make_float4(fa.x, fa.y, fb.x, fb.y);
    }
}

// ---------------------------------------------------------------------------
// Launch graph (aux joins back to stream 0 before return):
//   main: coords -> prefix1 (ev_p1) -> fix2 -> perm
//         -> (wait ev_t) sample -> (wait ev_aux)  [join]
//   aux:  transpose (ev_t) -> init_pad -> scatter -> (wait ev_crd) geom
//         -> (wait ev_p1) zero_hist (ev_aux)
// ---------------------------------------------------------------------------
extern "C" void kernel_launch(void* const* d_in, const int* in_sizes, int n_in,
                              void* d_out, int out_size) {
    const float* fm      = (const float*)d_in[0];
    const float* v2d     = (const float*)d_in[1];
    const float* v3d     = (const float*)d_in[2];
    const int*   parents = (const int*)  d_in[3];
    const float* bary    = (const float*)d_in[4];
    (void)in_sizes; (void)n_in; (void)out_size;

    float* out       = (float*)d_out;
    float* out_feats = out;                                    // (B,N,C)
    float* out_vw    = out + (size_t)BNUM * NPTS * CCH;        // (B,N)
    float* out_c3    = out_vw + (size_t)BNUM * NPTS;           // (B,N,3)

    static cudaStream_t aux = nullptr;
    static cudaEvent_t  ev_root = nullptr, ev_crd = nullptr, ev_p1 = nullptr,
                        ev_t = nullptr, ev_aux = nullptr;
    if (aux == nullptr) {
        cudaStreamCreateWithFlags(&aux, cudaStreamNonBlocking);
        cudaEventCreateWithFlags(&ev_root, cudaEventDisableTiming);
        cudaEventCreateWithFlags(&ev_crd,  cudaEventDisableTiming);
        cudaEventCreateWithFlags(&ev_p1,   cudaEventDisableTiming);
        cudaEventCreateWithFlags(&ev_t,    cudaEventDisableTiming);
        cudaEventCreateWithFlags(&ev_aux,  cudaEventDisableTiming);
    }

    // fork
    cudaEventRecord(ev_root, 0);
    cudaStreamWaitEvent(aux, ev_root, 0);

    // aux: transpose, depth init + vertex pad, depth scatter
    transpose_k<<<dim3(HWF / 128, CCH / 32, BNUM), dim3(32, 8), 0, aux>>>(fm);
    cudaEventRecord(ev_t, aux);
    init_pad_k<<<(BNUM * HWIMG / 4 + 255) / 256, 256, 0, aux>>>(v3d);
    scatter_k<<<(BNUM * NV + 255) / 256, 256, 0, aux>>>(v2d, v3d);

    // main critical path: coords (2 pts/thread) -> prefix1 -> fix2 -> perm
    coords_k<<<(NPT / 2 + 255) / 256, 256>>>(v2d, parents, bary);
    cudaEventRecord(ev_crd, 0);
    prefix1_k<<<NSBLK, 1024>>>();
    cudaEventRecord(ev_p1, 0);
    fix2_k<<<NSBLK, 1024>>>();
    perm_k<<<(NPT + 255) / 256, 256>>>();

    // aux: geometry (needs coords' centers + depth map), then hist cleanup
    cudaStreamWaitEvent(aux, ev_crd, 0);
    geom_k<<<(NPT + 255) / 256, 256, 0, aux>>>(parents, bary, out_vw, out_c3);
    cudaStreamWaitEvent(aux, ev_p1, 0);
    zero_hist_k<<<NBINS / 4 / 256, 256, 0, aux>>>();
    cudaEventRecord(ev_aux, aux);

    // main: sample needs transpose + sorted order
    cudaStreamWaitEvent(0, ev_t, 0);
    sample_k<<<NBINS / 8, 256>>>(out_feats);

    // join aux back into stream 0 (required for graph capture; free at runtime)
    cudaStreamWaitEvent(0, ev_aux, 0);
}